// round 11
// baseline (speedup 1.0000x reference)
#include <cuda_runtime.h>
#include <cuda_fp16.h>
#include <cstdint>

#define BH    64
#define T_LEN 4096
#define D_DIM 128
#define SPLIT 8
#define CHUNK (T_LEN / SPLIT)   // 512

// ---- phase A staging geometry ----
#define STG_A  16                         // t-rows per stage
#define RING_A 5
#define NSTG_A (CHUNK / STG_A)            // 32
#define ASTR   136                        // fp16 tile row stride (halves)
#define A_KR   0
#define A_VR   (RING_A * STG_A * D_DIM * 4)              // 40960
#define A_KH   (2 * RING_A * STG_A * D_DIM * 4)          // 81920
#define A_VH   (A_KH + 2 * STG_A * ASTR * 2)             // +8704
#define A_TOT  (A_VH + 2 * STG_A * ASTR * 2)             // 99328

// ---- phase B staging geometry ----
#define RING_B 3
#define PAD    136                        // KV fp16 stride (halves)
#define QSTR   36                        // Q fp16 slab stride (halves)
#define B_QR   0
#define B_WS   (RING_B * 128 * 32 * 4)                   // 49152
#define B_QH   (B_WS + 128 * PAD * 2)                    // +34816
#define B_TOT  (B_QH + 2 * 128 * QSTR * 2)               // 102400

#define SM_TOT B_TOT                      // union of role layouts

// ---- grid roles (dispatch order: producers first) ----
#define N_A    512                        // A: idx 0..511      (bh = idx>>3)
#define N_R    64                         // R: idx 512..575    (bh = idx-512)
#define N_B    1024                       // B: idx 576..1599   (2 t-tiles each)

// Scratch + flags (static device arrays — no allocs; zero-init, self-resetting).
__device__ __half g_kvph[SPLIT * BH * D_DIM * D_DIM]; // 16.75 MB fp16 partials
__device__ uint4  g_kvh4[BH * D_DIM * D_DIM / 8];     // 2 MB fp16 KV^T
__device__ int    g_flagA[BH];
__device__ int    g_flagR[BH];
__device__ int    g_flagB[BH];

// ---- helpers ----
__device__ __forceinline__ void mma16816(float* c, const uint32_t* a,
                                         const uint32_t* b) {
    asm volatile(
        "mma.sync.aligned.m16n8k16.row.col.f32.f16.f16.f32 "
        "{%0,%1,%2,%3}, {%4,%5,%6,%7}, {%8,%9}, {%0,%1,%2,%3};"
        : "+f"(c[0]), "+f"(c[1]), "+f"(c[2]), "+f"(c[3])
        : "r"(a[0]), "r"(a[1]), "r"(a[2]), "r"(a[3]), "r"(b[0]), "r"(b[1]));
}
__device__ __forceinline__ void ldsm_x4_t(uint32_t* r, uint32_t addr) {
    asm volatile(
        "ldmatrix.sync.aligned.m8n8.x4.trans.shared.b16 {%0,%1,%2,%3}, [%4];"
        : "=r"(r[0]), "=r"(r[1]), "=r"(r[2]), "=r"(r[3]) : "r"(addr));
}
__device__ __forceinline__ uint32_t smem_u32(const void* p) {
    uint32_t a;
    asm("{ .reg .u64 t; cvta.to.shared.u64 t, %1; cvt.u32.u64 %0, t; }"
        : "=r"(a) : "l"(p));
    return a;
}
__device__ __forceinline__ uint2 cvt4h(float4 f) {
    __half2 h0 = __floats2half2_rn(f.x, f.y);
    __half2 h1 = __floats2half2_rn(f.z, f.w);
    uint2 u;
    u.x = *reinterpret_cast<unsigned int*>(&h0);
    u.y = *reinterpret_cast<unsigned int*>(&h1);
    return u;
}
__device__ __forceinline__ uint32_t cvt2h(float a, float b) {
    __half2 h = __floats2half2_rn(a, b);
    return *reinterpret_cast<unsigned int*>(&h);
}
__device__ __forceinline__ void cp16(uint32_t smem_dst, const void* gsrc) {
    asm volatile("cp.async.cg.shared.global [%0], [%1], 16;"
                 :: "r"(smem_dst), "l"(gsrc) : "memory");
}
#define CP_COMMIT() asm volatile("cp.async.commit_group;" ::: "memory")

// ============================================================================
// Role A: KV^T partials via HMMA (cp.async 5-deep fp32 ring + fp16 hop).
// ============================================================================
__device__ void role_A(int cta, const float* __restrict__ K,
                       const float* __restrict__ V, char* sma) {
    float*  Kr = (float*)(sma + A_KR);
    float*  Vr = (float*)(sma + A_VR);
    __half* Kh = (__half*)(sma + A_KH);
    __half* Vh = (__half*)(sma + A_VH);

    const int tid = threadIdx.x;
    const int bh = cta >> 3;
    const int split = cta & 7;
    const int t0c = split * CHUNK;
    const float4* Kg4 = (const float4*)(K + (size_t)bh * T_LEN * D_DIM);
    const float4* Vg4 = (const float4*)(V + (size_t)bh * T_LEN * D_DIM);

    const uint32_t kr_base = smem_u32(Kr);
    const uint32_t vr_base = smem_u32(Vr);
    const uint32_t kh_base = smem_u32(Kh);
    const uint32_t vh_base = smem_u32(Vh);

    const int wid = tid >> 5;
    const int l   = tid & 31;
    const int g   = l >> 2;
    const int q2  = (l & 3) * 2;
    const int wm  = (wid & 3) * 32;
    const int wn  = (wid >> 2) * 64;
    const int a_row = (l & 7) + 8 * (l >> 4);
    const int a_col = wm + 8 * ((l >> 3) & 1);
    const int b_row = (l & 7) + 8 * ((l >> 3) & 1);
    const int b_col = wn + 8 * (l >> 4);

    float acc[2][8][4];
    #pragma unroll
    for (int i = 0; i < 2; i++)
        #pragma unroll
        for (int j = 0; j < 8; j++)
            #pragma unroll
            for (int v = 0; v < 4; v++) acc[i][j][v] = 0.f;

    auto issue = [&](int stg) {
        if (stg < NSTG_A) {
            const int slot = stg % RING_A;
            const float4* Kgs = Kg4 + (size_t)(t0c + stg * STG_A) * 32;
            const float4* Vgs = Vg4 + (size_t)(t0c + stg * STG_A) * 32;
            #pragma unroll
            for (int i = 0; i < 2; i++) {
                int lin = tid + 256 * i;
                cp16(kr_base + (slot * 512 + lin) * 16, &Kgs[lin]);
                cp16(vr_base + (slot * 512 + lin) * 16, &Vgs[lin]);
            }
        }
        CP_COMMIT();
    };

    #pragma unroll
    for (int p = 0; p < RING_A - 1; p++) issue(p);

    for (int s = 0; s < NSTG_A; s++) {
        asm volatile("cp.async.wait_group %0;" :: "n"(RING_A - 2) : "memory");
        __syncthreads();

        const int slot = s % RING_A;
        const int buf = s & 1;
        #pragma unroll
        for (int i = 0; i < 2; i++) {
            int lin = tid + 256 * i;
            int t = lin >> 5, c4 = lin & 31;
            float4 kf = *(const float4*)&Kr[slot * 512 * 4 + lin * 4];
            float4 vf = *(const float4*)&Vr[slot * 512 * 4 + lin * 4];
            *(uint2*)&Kh[buf * STG_A * ASTR + t * ASTR + c4 * 4] = cvt4h(kf);
            *(uint2*)&Vh[buf * STG_A * ASTR + t * ASTR + c4 * 4] = cvt4h(vf);
        }
        issue(s + RING_A - 1);
        __syncthreads();

        const uint32_t kb = kh_base + buf * STG_A * ASTR * 2;
        const uint32_t vb = vh_base + buf * STG_A * ASTR * 2;
        uint32_t af[2][4];
        #pragma unroll
        for (int mi = 0; mi < 2; mi++)
            ldsm_x4_t(af[mi], vb + (a_row * ASTR + a_col + 16 * mi) * 2);
        uint32_t bf[4][4];
        #pragma unroll
        for (int nj = 0; nj < 4; nj++)
            ldsm_x4_t(bf[nj], kb + (b_row * ASTR + b_col + 16 * nj) * 2);
        #pragma unroll
        for (int mi = 0; mi < 2; mi++)
            #pragma unroll
            for (int ni = 0; ni < 8; ni++)
                mma16816(acc[mi][ni], af[mi], &bf[ni >> 1][(ni & 1) * 2]);
    }

    __half* gp = g_kvph + ((size_t)split * BH + bh) * D_DIM * D_DIM;
    #pragma unroll
    for (int mi = 0; mi < 2; mi++) {
        #pragma unroll
        for (int ni = 0; ni < 8; ni++) {
            int r = wm + mi * 16 + g;
            int c = wn + ni * 8 + q2;
            *(uint32_t*)&gp[r * D_DIM + c]       = cvt2h(acc[mi][ni][0], acc[mi][ni][1]);
            *(uint32_t*)&gp[(r + 8) * D_DIM + c] = cvt2h(acc[mi][ni][2], acc[mi][ni][3]);
        }
    }

    __syncthreads();
    if (tid == 0) {
        __threadfence();
        atomicAdd(&g_flagA[bh], 1);
    }
}

// ============================================================================
// Role R: per-bh reducer — wait for 8 A-CTAs, reduce partials -> fp16 KV^T.
// ============================================================================
__device__ void role_R(int bh) {
    const int tid = threadIdx.x;
    if (tid == 0)
        while (atomicAdd(&g_flagA[bh], 0) < SPLIT) __nanosleep(200);
    __syncthreads();
    __threadfence();

    const uint4* p4 = (const uint4*)g_kvph;
    #pragma unroll
    for (int i = 0; i < 8; i++) {
        int lin = tid + 256 * i;                  // 2048 uint4 per bh
        float s[8];
        #pragma unroll
        for (int v = 0; v < 8; v++) s[v] = 0.f;
        #pragma unroll
        for (int p = 0; p < SPLIT; p++) {
            uint4 u = p4[((size_t)p * BH + bh) * 2048 + lin];
            const unsigned int w[4] = {u.x, u.y, u.z, u.w};
            #pragma unroll
            for (int j = 0; j < 4; j++) {
                __half2 h = *reinterpret_cast<const __half2*>(&w[j]);
                float2 f = __half22float2(h);
                s[2 * j] += f.x; s[2 * j + 1] += f.y;
            }
        }
        uint4 o;
        o.x = cvt2h(s[0], s[1]); o.y = cvt2h(s[2], s[3]);
        o.z = cvt2h(s[4], s[5]); o.w = cvt2h(s[6], s[7]);
        g_kvh4[(size_t)bh * 2048 + lin] = o;
    }

    __syncthreads();
    if (tid == 0) {
        __threadfence();
        atomicExch(&g_flagR[bh], 1);
    }
}

// ============================================================================
// Role B: out = Q @ KV, 2 t-tiles per CTA. Q slabs 0-1 prefetched BEFORE the
// dependency wait (Q is flag-independent); KV issued after the flag.
// Group order: g0=Q0, g1=Q1, g2=KV, g(3+ks)=Q(ks+2).
// ============================================================================
__device__ void role_B(int j, const float* __restrict__ Q,
                       float* __restrict__ out, char* smb) {
    float*  Qr = (float*)(smb + B_QR);
    __half* Ws = (__half*)(smb + B_WS);
    __half* Qh = (__half*)(smb + B_QH);

    const int tid = threadIdx.x;
    const int bh = j >> 4;
    const int pair = j & 15;                 // tiles pair*2, pair*2+1

    const uint32_t qr_base = smem_u32(Qr);
    const uint32_t ws_base = smem_u32(Ws);

    const float4* Qt[2];
    Qt[0] = (const float4*)(Q + ((size_t)bh * T_LEN + (pair * 2) * 128) * D_DIM);
    Qt[1] = (const float4*)(Q + ((size_t)bh * T_LEN + (pair * 2 + 1) * 128) * D_DIM);

    auto issueQ = [&](int stg) {             // 8 slabs: tile = stg>>2, d-slab = stg&3
        if (stg < 8) {
            const int slot = stg % RING_B;
            const float4* qb = Qt[stg >> 2];
            const int d8 = (stg & 3) * 8;
            #pragma unroll
            for (int i = 0; i < 4; i++) {
                int lin = tid + 256 * i;
                int row = lin >> 3, c4 = lin & 7;
                cp16(qr_base + (slot * 1024 + lin) * 16, &qb[row * 32 + d8 + c4]);
            }
        }
    };

    // ---- flag-independent prefetch: Q slabs 0,1 stream during the wait ----
    issueQ(0); CP_COMMIT();                  // g0
    issueQ(1); CP_COMMIT();                  // g1

    if (tid == 0)
        while (atomicAdd(&g_flagR[bh], 0) == 0) __nanosleep(200);
    __syncthreads();

    // ---- KV tile (flag-dependent) ----
    {
        const uint4* Bg = g_kvh4 + (size_t)bh * 2048;
        #pragma unroll
        for (int u = 0; u < 8; u++) {
            int idx = tid + 256 * u;
            int row = idx >> 4, c8 = idx & 15;
            cp16(ws_base + (row * PAD + c8 * 8) * 2, &Bg[row * 16 + c8]);
        }
        CP_COMMIT();                         // g2
    }

    const int wid = tid >> 5;
    const int l   = tid & 31;
    const int g   = l >> 2;
    const int q2  = (l & 3) * 2;
    const int wm  = (wid & 3) * 32;
    const int wn  = (wid >> 2) * 64;

    float acc[2][8][4];
    #pragma unroll
    for (int i = 0; i < 2; i++)
        #pragma unroll
        for (int jj = 0; jj < 8; jj++)
            #pragma unroll
            for (int v = 0; v < 4; v++) acc[i][jj][v] = 0.f;

    for (int ks = 0; ks < 8; ks++) {
        // ks=0: need g0(Q0)+g2(KV): full drain. ks>=1: slab ks is in-order
        // complete once all-but-newest groups are done.
        if (ks == 0)
            asm volatile("cp.async.wait_group 0;" ::: "memory");
        else
            asm volatile("cp.async.wait_group 1;" ::: "memory");
        __syncthreads();

        const int slot = ks % RING_B;
        const int buf = ks & 1;
        #pragma unroll
        for (int i = 0; i < 4; i++) {
            int lin = tid + 256 * i;
            int row = lin >> 3, c4 = lin & 7;
            float4 f = *(const float4*)&Qr[slot * 4096 + lin * 4];
            *(uint2*)&Qh[buf * 128 * QSTR + row * QSTR + c4 * 4] = cvt4h(f);
        }
        issueQ(ks + 2);
        CP_COMMIT();                         // g(3+ks)
        __syncthreads();

        const __half* Qb = Qh + buf * 128 * QSTR;
        const int kbase = (ks & 3) * 32;
        #pragma unroll
        for (int kl = 0; kl < 32; kl += 16) {
            const int k0 = kbase + kl;
            uint32_t af[2][4];
            #pragma unroll
            for (int mi = 0; mi < 2; mi++) {
                int r = wm + mi * 16 + g;
                af[mi][0] = *(const uint32_t*)&Qb[r * QSTR + kl + q2];
                af[mi][1] = *(const uint32_t*)&Qb[(r + 8) * QSTR + kl + q2];
                af[mi][2] = *(const uint32_t*)&Qb[r * QSTR + kl + q2 + 8];
                af[mi][3] = *(const uint32_t*)&Qb[(r + 8) * QSTR + kl + q2 + 8];
            }
            #pragma unroll
            for (int ni = 0; ni < 8; ni++) {
                int e = wn + ni * 8 + g;
                uint32_t bf[2];
                bf[0] = *(const uint32_t*)&Ws[e * PAD + k0 + q2];
                bf[1] = *(const uint32_t*)&Ws[e * PAD + k0 + q2 + 8];
                mma16816(acc[0][ni], af[0], bf);
                mma16816(acc[1][ni], af[1], bf);
            }
        }

        if ((ks & 3) == 3) {                 // tile (ks>>2) complete: store
            float* Ob = out +
                ((size_t)bh * T_LEN + (pair * 2 + (ks >> 2)) * 128) * D_DIM;
            #pragma unroll
            for (int mi = 0; mi < 2; mi++) {
                #pragma unroll
                for (int ni = 0; ni < 8; ni++) {
                    int r = wm + mi * 16 + g;
                    int c = wn + ni * 8 + q2;
                    *(float2*)&Ob[(size_t)r * D_DIM + c] =
                        make_float2(acc[mi][ni][0], acc[mi][ni][1]);
                    *(float2*)&Ob[(size_t)(r + 8) * D_DIM + c] =
                        make_float2(acc[mi][ni][2], acc[mi][ni][3]);
                    #pragma unroll
                    for (int v = 0; v < 4; v++) acc[mi][ni][v] = 0.f;
                }
            }
        }
    }

    // ---- self-reset: last of the 16 B CTAs for this bh zeroes the flags.
    // Safe: all flagA/flagR readers for bh have passed their waits before
    // the 16th increment can occur. Leaves all flags at 0 for the next
    // graph replay (no separate reset kernel needed).
    __syncthreads();
    if (tid == 0) {
        int c = atomicAdd(&g_flagB[bh], 1);
        if (c == 15) {
            g_flagA[bh] = 0;
            g_flagR[bh] = 0;
            g_flagB[bh] = 0;
            __threadfence();
        }
    }
}

// ============================================================================
__global__ __launch_bounds__(256, 2) void fused(const float* __restrict__ Q,
                                                const float* __restrict__ K,
                                                const float* __restrict__ V,
                                                float* __restrict__ out) {
    extern __shared__ char smx[];
    const int cta = blockIdx.x;
    if (cta < N_A) {
        role_A(cta, K, V, smx);
    } else if (cta < N_A + N_R) {
        role_R(cta - N_A);
    } else {
        role_B(cta - N_A - N_R, Q, out, smx);
    }
}

extern "C" void kernel_launch(void* const* d_in, const int* in_sizes, int n_in,
                              void* d_out, int out_size) {
    const float* Q = (const float*)d_in[0];
    const float* K = (const float*)d_in[1];
    const float* V = (const float*)d_in[2];
    float* out = (float*)d_out;

    cudaFuncSetAttribute(fused,
                         cudaFuncAttributeMaxDynamicSharedMemorySize, SM_TOT);
    fused<<<N_A + N_R + N_B, 256, SM_TOT>>>(Q, K, V, out);
}